// round 11
// baseline (speedup 1.0000x reference)
#include <cuda_runtime.h>
#include <math.h>
#include <stdio.h>
#include <assert.h>

#define Vv 30000
#define Ee 300
#define Hd 300
#define G4 1200
#define Td 9
#define Bd 256
#define Sd 256

#define HT 20    // h per block (15 tiles * 20 = 300)
#define NHT 15
#define BT 64    // batch per block
#define NBT 4

// ---- scratch (device globals) ----
__device__ float  g_table_f[(size_t)Vv * G4];
__device__ float  g_table_b[(size_t)Vv * G4];
__device__ float  g_hf[(size_t)Sd * Hd * Bd];   // layout [time][h][b]
__device__ float  g_hb[(size_t)Sd * Hd * Bd];
__device__ double g_em[(size_t)Sd * Bd * Td];
__device__ unsigned char g_bp[(size_t)(Sd - 1) * Bd * Td];
__device__ unsigned g_bar[8];                    // group barriers [dir*4+btile]

__device__ __forceinline__ float clampg(float v) {
    return fmaxf(fminf(v, 30.f), -30.f);
}

// f32x2 packed fma: d = a*b + d  (two independent fp32 FMAs, exact rounding)
__device__ __forceinline__ void fma2(unsigned long long& d,
                                     unsigned long long a, unsigned long long b) {
    asm("fma.rn.f32x2 %0, %1, %2, %0;" : "+l"(d) : "l"(a), "l"(b));
}
__device__ __forceinline__ float2 u2f(unsigned long long v) {
    float2 r;
    asm("mov.b64 {%0, %1}, %2;" : "=f"(r.x), "=f"(r.y) : "l"(v));
    return r;
}

struct SizePack { int n; int v[16]; };
__global__ void bad_layout_kernel(SizePack sp)
{
    printf("[diag] LAYOUT MISMATCH n_in=%d sizes:", sp.n);
    for (int i = 0; i < 16 && i < sp.n; i++) printf(" %d", sp.v[i]);
    printf("\n");
    assert(0);
}

__global__ void zero_bar_kernel()
{
    if (threadIdx.x < 8) g_bar[threadIdx.x] = 0;
}

// ============================================================
// Phase 1: vocab gate table. C[m][n] = sum_k emb[m][k]*W[n][k] + b1[n]+b2[n]
// 128x128 tile, 8x8 micro, f32x2. grid (10, 235, 2). 256 thr.
// ============================================================
__global__ void __launch_bounds__(256)
table_gemm(const float* __restrict__ A,
           const float* __restrict__ Wf, const float* __restrict__ Wb,
           const float* __restrict__ b1f, const float* __restrict__ b2f,
           const float* __restrict__ b1b, const float* __restrict__ b2b)
{
    int dir = blockIdx.z;
    const float* W  = dir ? Wb  : Wf;
    const float* b1 = dir ? b1b : b1f;
    const float* b2 = dir ? b2b : b2f;
    float* C = dir ? g_table_b : g_table_f;

    __shared__ __align__(16) float As2[16 * 264];  // [kk][2*m] m-duplicated
    __shared__ __align__(16) float Wsm[16 * 132];  // [kk][n]

    int n0 = blockIdx.x * 128;
    int m0 = blockIdx.y * 128;
    int tid = threadIdx.x;
    int tx = tid & 15;     // n octet
    int ty = tid >> 4;     // m octet
    int r  = tid & 127;    // stage row
    int part = tid >> 7;   // 0/1

    unsigned long long acc[8][4];
#pragma unroll
    for (int i = 0; i < 8; i++)
#pragma unroll
        for (int p = 0; p < 4; p++) acc[i][p] = 0ull;

    for (int k0 = 0; k0 < Ee; k0 += 16) {
        __syncthreads();
        // stage A rows (m) with duplication
        {
            int m = m0 + r;
#pragma unroll
            for (int j = 0; j < 2; j++) {
                int k = k0 + part * 8 + j * 4;
                float4 v = make_float4(0.f, 0.f, 0.f, 0.f);
                if (m < Vv && k + 3 < Ee)
                    v = *(const float4*)&A[(size_t)m * Ee + k];
                int kk = part * 8 + j * 4;
                float* dst0 = &As2[kk * 264 + 2 * r];
                *(float2*)(dst0)           = make_float2(v.x, v.x);
                *(float2*)(dst0 + 264)     = make_float2(v.y, v.y);
                *(float2*)(dst0 + 2 * 264) = make_float2(v.z, v.z);
                *(float2*)(dst0 + 3 * 264) = make_float2(v.w, v.w);
            }
        }
        // stage W rows (n)
        {
            int n = n0 + r;
#pragma unroll
            for (int j = 0; j < 2; j++) {
                int k = k0 + part * 8 + j * 4;
                float4 v = make_float4(0.f, 0.f, 0.f, 0.f);
                if (n < G4 && k + 3 < Ee)
                    v = *(const float4*)&W[(size_t)n * Ee + k];
                int kk = part * 8 + j * 4;
                Wsm[kk * 132 + r]           = v.x;
                Wsm[(kk + 1) * 132 + r]     = v.y;
                Wsm[(kk + 2) * 132 + r]     = v.z;
                Wsm[(kk + 3) * 132 + r]     = v.w;
            }
        }
        __syncthreads();
#pragma unroll 4
        for (int kk = 0; kk < 16; kk++) {
            const float* arow = &As2[kk * 264 + ty * 16];
            const float* wrow = &Wsm[kk * 132 + tx * 8];
            ulonglong2 a01 = *(const ulonglong2*)(arow);
            ulonglong2 a23 = *(const ulonglong2*)(arow + 4);
            ulonglong2 a45 = *(const ulonglong2*)(arow + 8);
            ulonglong2 a67 = *(const ulonglong2*)(arow + 12);
            ulonglong2 w03 = *(const ulonglong2*)(wrow);
            ulonglong2 w47 = *(const ulonglong2*)(wrow + 4);
            unsigned long long av[8] = {a01.x, a01.y, a23.x, a23.y,
                                        a45.x, a45.y, a67.x, a67.y};
            unsigned long long wv[4] = {w03.x, w03.y, w47.x, w47.y};
#pragma unroll
            for (int i = 0; i < 8; i++)
#pragma unroll
                for (int p = 0; p < 4; p++) fma2(acc[i][p], av[i], wv[p]);
        }
    }

    // epilogue
    float bias[8];
#pragma unroll
    for (int j = 0; j < 8; j++) {
        int n = n0 + tx * 8 + j;
        bias[j] = (n < G4) ? (b1[n] + b2[n]) : 0.f;
    }
#pragma unroll
    for (int i = 0; i < 8; i++) {
        int m = m0 + ty * 8 + i;
        if (m >= Vv) continue;
        float vals[8];
#pragma unroll
        for (int p = 0; p < 4; p++) {
            float2 u = u2f(acc[i][p]);
            vals[2 * p]     = u.x + bias[2 * p];
            vals[2 * p + 1] = u.y + bias[2 * p + 1];
        }
        int nb = n0 + tx * 8;
        if (nb + 7 < G4) {
            *(float4*)&C[(size_t)m * G4 + nb]     = make_float4(vals[0], vals[1], vals[2], vals[3]);
            *(float4*)&C[(size_t)m * G4 + nb + 4] = make_float4(vals[4], vals[5], vals[6], vals[7]);
        } else {
#pragma unroll
            for (int j = 0; j < 8; j++)
                if (nb + j < G4) C[(size_t)m * G4 + nb + j] = vals[j];
        }
    }
}

// ============================================================
// Phase 2: PERSISTENT bidirectional LSTM recurrence.
// grid (15,4,2) = 120 blocks (all resident), 320 threads.
// Block owns h-tile [h0,h0+20) x b-tile [b0,b0+64) for one direction.
// w_hh tile in smem for all 256 steps; c-state in registers.
// Group barrier: 15 h-blocks per (dir,btile) sync via global atomic.
// ============================================================
__global__ void __launch_bounds__(320)
lstm_persist(const int* __restrict__ x,
             const float* __restrict__ whhf, const float* __restrict__ whhb)
{
    extern __shared__ float smem[];
    float* Ws  = smem;           // [300][80]: k-major, (hl*4+g) inner
    float* Hs2 = smem + 24000;   // [60][132]: k-chunk rows, b-duplicated

    int htile = blockIdx.x;
    int btile = blockIdx.y;
    int dir   = blockIdx.z;
    int h0 = htile * HT;
    int b0 = btile * BT;

    const float* whh = dir ? whhb : whhf;
    const float* tbl = dir ? g_table_b : g_table_f;
    float* hbase = dir ? g_hb : g_hf;
    unsigned* bar = &g_bar[dir * 4 + btile];

    int tid = threadIdx.x;
    int tx = tid % HT;        // h lane (0..19)
    int ty = tid / HT;        // b quad (0..15)
    int h  = h0 + tx;

    // --- load W tile once: Ws[k*80 + hl*4 + g] = whh[(g*300 + h0+hl)*300 + k]
    for (int idx = tid; idx < HT * 4 * Hd; idx += 320) {
        int k = idx % Hd;
        int q = idx / Hd;            // hl*4+g
        int g = q & 3, hl = q >> 2;
        Ws[k * 80 + q] = whh[((size_t)g * Hd + h0 + hl) * Hd + k];
    }
    __syncthreads();

    float cst[4] = {0.f, 0.f, 0.f, 0.f};

    for (int s = 0; s < Sd; s++) {
        int time = dir ? (Sd - 1 - s) : s;

        // prefetch tokens + table rows (consumed in epilogue; hidden by GEMM)
        int bb = b0 + ty * 4;
        float tv[4][4];
#pragma unroll
        for (int i = 0; i < 4; i++) {
            int t = __ldg(&x[(bb + i) * Sd + time]);
            if ((unsigned)t >= (unsigned)Vv) t = 0;
            const float* trow = tbl + (size_t)t * G4 + h;
#pragma unroll
            for (int g = 0; g < 4; g++) tv[i][g] = __ldg(trow + g * Hd);
        }

        unsigned long long acc[4][2] = {{0ull,0ull},{0ull,0ull},{0ull,0ull},{0ull,0ull}};

        if (s > 0) {
            int ptime = dir ? (time + 1) : (time - 1);
            const float* hprev = hbase + (size_t)ptime * Hd * Bd;
            for (int k0 = 0; k0 < Hd; k0 += 60) {
                __syncthreads();
                // stage 60 k-rows of h, b-duplicated
#pragma unroll
                for (int l = 0; l < 3; l++) {
                    int j = tid + l * 320;         // 0..959
                    int c = j >> 4, r = j & 15;
                    float4 v = *(const float4*)&hprev[(size_t)(k0 + c) * Bd + b0 + r * 4];
                    float* dst = &Hs2[c * 132 + r * 8];
                    *(float4*)dst       = make_float4(v.x, v.x, v.y, v.y);
                    *(float4*)(dst + 4) = make_float4(v.z, v.z, v.w, v.w);
                }
                __syncthreads();
#pragma unroll 6
                for (int kk = 0; kk < 60; kk++) {
                    ulonglong2 w03 = *(const ulonglong2*)&Ws[(k0 + kk) * 80 + tx * 4];
                    const float* hrow = &Hs2[kk * 132 + ty * 8];
                    ulonglong2 h01 = *(const ulonglong2*)(hrow);
                    ulonglong2 h23 = *(const ulonglong2*)(hrow + 4);
                    fma2(acc[0][0], h01.x, w03.x); fma2(acc[0][1], h01.x, w03.y);
                    fma2(acc[1][0], h01.y, w03.x); fma2(acc[1][1], h01.y, w03.y);
                    fma2(acc[2][0], h23.x, w03.x); fma2(acc[2][1], h23.x, w03.y);
                    fma2(acc[3][0], h23.y, w03.x); fma2(acc[3][1], h23.y, w03.y);
                }
            }
        }

        // epilogue: gates -> activations -> h,c
        float hnew[4];
#pragma unroll
        for (int i = 0; i < 4; i++) {
            float2 p0 = u2f(acc[i][0]);   // (gate_i, gate_f)
            float2 p1 = u2f(acc[i][1]);   // (gate_g, gate_o)
            float ai = clampg(p0.x + tv[i][0]);
            float af = clampg(p0.y + tv[i][1]);
            float ag = clampg(p1.x + tv[i][2]);
            float ao = clampg(p1.y + tv[i][3]);
            float ig = 1.f / (1.f + expf(-ai));
            float fg = 1.f / (1.f + expf(-af));
            float gg = tanhf(ag);
            float og = 1.f / (1.f + expf(-ao));
            float cnew = fg * cst[i] + ig * gg;
            cst[i] = cnew;
            hnew[i] = og * tanhf(clampg(cnew));
        }
        *(float4*)&hbase[((size_t)time * Hd + h) * Bd + b0 + ty * 4] =
            make_float4(hnew[0], hnew[1], hnew[2], hnew[3]);

        // group barrier (15 blocks sharing dir+btile)
        if (s < Sd - 1) {
            __threadfence();
            __syncthreads();
            if (tid == 0) {
                unsigned target = (unsigned)NHT * (s + 1);
                unsigned v = atomicAdd(bar, 1u) + 1u;
                if (v < target) {
                    while (atomicAdd(bar, 0u) < target) __nanosleep(64);
                }
            }
            __syncthreads();
            __threadfence();
        }
    }
}

// ============================================================
// Phase 3a: emissions, fp64 accumulation. Block per s, thread per b.
// h layout [s][h][b] -> coalesced reads.
// ============================================================
__global__ void __launch_bounds__(256)
emis_kernel(const float* __restrict__ wproj, const float* __restrict__ bproj)
{
    __shared__ float wp[Td * 2 * Hd];   // 21.6KB
    int s = blockIdx.x;
    int b = threadIdx.x;
    for (int i = threadIdx.x; i < Td * 2 * Hd; i += blockDim.x) wp[i] = wproj[i];
    __syncthreads();

    const float* f  = g_hf + (size_t)s * Hd * Bd;
    const float* bk = g_hb + (size_t)s * Hd * Bd;
    double acc[Td] = {};
    for (int j = 0; j < Hd; j++) {
        double v = (double)f[(size_t)j * Bd + b];
#pragma unroll
        for (int t = 0; t < Td; t++) acc[t] += v * (double)wp[t * 2 * Hd + j];
    }
    for (int j = 0; j < Hd; j++) {
        double v = (double)bk[(size_t)j * Bd + b];
#pragma unroll
        for (int t = 0; t < Td; t++) acc[t] += v * (double)wp[t * 2 * Hd + Hd + j];
    }
#pragma unroll
    for (int t = 0; t < Td; t++)
        g_em[((size_t)s * Bd + b) * Td + t] = acc[t] + (double)bproj[t];
}

// ============================================================
// Phase 3b: Viterbi DP + backtrack, fp64, float32 tag output.
// ============================================================
__global__ void viterbi_kernel(const float* __restrict__ start_t, const float* __restrict__ end_t,
                               const float* __restrict__ trans, float* __restrict__ out)
{
    __shared__ double tr[Td][Td];
    if (threadIdx.x < Td * Td)
        tr[threadIdx.x / Td][threadIdx.x % Td] = (double)trans[threadIdx.x];
    __syncthreads();
    int b = blockIdx.x * blockDim.x + threadIdx.x;
    if (b >= Bd) return;

    double sc[Td];
#pragma unroll
    for (int t = 0; t < Td; t++)
        sc[t] = (double)start_t[t] + g_em[(size_t)b * Td + t];

    for (int s = 1; s < Sd; s++) {
        const double* em = &g_em[((size_t)s * Bd + b) * Td];
        double ns[Td];
#pragma unroll
        for (int tn = 0; tn < Td; tn++) {
            double best = sc[0] + tr[0][tn];
            int arg = 0;
#pragma unroll
            for (int tp = 1; tp < Td; tp++) {
                double v = sc[tp] + tr[tp][tn];
                if (v > best) { best = v; arg = tp; }
            }
            ns[tn] = best + em[tn];
            g_bp[((size_t)(s - 1) * Bd + b) * Td + tn] = (unsigned char)arg;
        }
#pragma unroll
        for (int t = 0; t < Td; t++) sc[t] = ns[t];
    }

    int last = 0;
    double best = sc[0] + (double)end_t[0];
#pragma unroll
    for (int t = 1; t < Td; t++) {
        double v = sc[t] + (double)end_t[t];
        if (v > best) { best = v; last = t; }
    }
    out[b * Sd + (Sd - 1)] = (float)last;
    int tag = last;
    for (int s = Sd - 2; s >= 0; s--) {
        tag = g_bp[((size_t)s * Bd + b) * Td + tag];
        out[b * Sd + s] = (float)tag;
    }
}

// ============================================================
extern "C" void kernel_launch(void* const* d_in, const int* in_sizes, int n_in,
                              void* d_out, int out_size)
{
    static const int expA[15] = {65536, 9000000, 360000, 360000, 1200, 1200,
                                 360000, 360000, 1200, 1200, 5400, 9, 9, 9, 81};
    bool okA = (n_in == 15), okA4 = (n_in == 15);
    for (int i = 0; i < 15 && n_in == 15; i++) {
        if (in_sizes[i] != expA[i])     okA  = false;
        if (in_sizes[i] != expA[i] * 4) okA4 = false;
    }
    if (!okA && !okA4) {
        SizePack sp; sp.n = n_in;
        for (int i = 0; i < 16; i++) sp.v[i] = (i < n_in) ? in_sizes[i] : -1;
        bad_layout_kernel<<<1, 1>>>(sp);
        return;
    }

    const int*   x       = (const int*)  d_in[0];
    const float* emb     = (const float*)d_in[1];
    const float* wihf    = (const float*)d_in[2];
    const float* whhf    = (const float*)d_in[3];
    const float* bihf    = (const float*)d_in[4];
    const float* bhhf    = (const float*)d_in[5];
    const float* wihb    = (const float*)d_in[6];
    const float* whhb    = (const float*)d_in[7];
    const float* bihb    = (const float*)d_in[8];
    const float* bhhb    = (const float*)d_in[9];
    const float* wproj   = (const float*)d_in[10];
    const float* bproj   = (const float*)d_in[11];
    const float* start_t = (const float*)d_in[12];
    const float* end_t   = (const float*)d_in[13];
    const float* trans   = (const float*)d_in[14];
    float* out = (float*)d_out;

    // reset group barriers (graph replays reuse device state)
    zero_bar_kernel<<<1, 32>>>();

    // Phase 1: vocab gate tables, both dirs in one launch
    dim3 gt((G4 + 127) / 128, (Vv + 127) / 128, 2);
    table_gemm<<<gt, 256>>>(emb, wihf, wihb, bihf, bhhf, bihb, bhhb);

    // Phase 2: persistent recurrence (single launch, 120 resident blocks)
    int smem_bytes = (24000 + 60 * 132) * sizeof(float);   // 127,680 B
    cudaFuncSetAttribute(lstm_persist,
                         cudaFuncAttributeMaxDynamicSharedMemorySize, smem_bytes);
    dim3 gp(NHT, NBT, 2);
    lstm_persist<<<gp, 320, smem_bytes>>>(x, whhf, whhb);

    // Phase 3: emissions + Viterbi
    emis_kernel<<<Sd, Bd>>>(wproj, bproj);
    viterbi_kernel<<<2, 128>>>(start_t, end_t, trans, out);
}

// round 12
// speedup vs baseline: 1.0234x; 1.0234x over previous
#include <cuda_runtime.h>
#include <math.h>
#include <stdio.h>
#include <assert.h>

#define Vv 30000
#define Ee 300
#define Hd 300
#define G4 1200
#define Td 9
#define Bd 256
#define Sd 256

#define HT 20    // h per block (15 tiles * 20 = 300)
#define NHT 15
#define BT 64    // batch per block
#define NBT 4

// ---- scratch (device globals) ----
__device__ float  g_table_f[(size_t)Vv * G4];
__device__ float  g_table_b[(size_t)Vv * G4];
__device__ float  g_hf[(size_t)Sd * Hd * Bd];   // layout [time][h][b]
__device__ float  g_hb[(size_t)Sd * Hd * Bd];
__device__ double g_em[(size_t)Sd * Bd * Td];
__device__ unsigned char g_bp[(size_t)(Sd - 1) * Bd * Td];
__device__ unsigned g_bar2[512];                 // [group*64]=cnt, [group*64+32]=flag

__device__ __forceinline__ float clampg(float v) {
    return fmaxf(fminf(v, 30.f), -30.f);
}

// f32x2 packed fma: d = a*b + d  (two independent fp32 FMAs, exact rounding)
__device__ __forceinline__ void fma2(unsigned long long& d,
                                     unsigned long long a, unsigned long long b) {
    asm("fma.rn.f32x2 %0, %1, %2, %0;" : "+l"(d) : "l"(a), "l"(b));
}
__device__ __forceinline__ float2 u2f(unsigned long long v) {
    float2 r;
    asm("mov.b64 {%0, %1}, %2;" : "=f"(r.x), "=f"(r.y) : "l"(v));
    return r;
}

struct SizePack { int n; int v[16]; };
__global__ void bad_layout_kernel(SizePack sp)
{
    printf("[diag] LAYOUT MISMATCH n_in=%d sizes:", sp.n);
    for (int i = 0; i < 16 && i < sp.n; i++) printf(" %d", sp.v[i]);
    printf("\n");
    assert(0);
}

__global__ void zero_bar_kernel()
{
    if (threadIdx.x < 512) g_bar2[threadIdx.x] = 0;
}

// ============================================================
// Phase 1: vocab gate table (unchanged from R11; ~0.5-1ms).
// ============================================================
__global__ void __launch_bounds__(256)
table_gemm(const float* __restrict__ A,
           const float* __restrict__ Wf, const float* __restrict__ Wb,
           const float* __restrict__ b1f, const float* __restrict__ b2f,
           const float* __restrict__ b1b, const float* __restrict__ b2b)
{
    int dir = blockIdx.z;
    const float* W  = dir ? Wb  : Wf;
    const float* b1 = dir ? b1b : b1f;
    const float* b2 = dir ? b2b : b2f;
    float* C = dir ? g_table_b : g_table_f;

    __shared__ __align__(16) float As2[16 * 264];
    __shared__ __align__(16) float Wsm[16 * 132];

    int n0 = blockIdx.x * 128;
    int m0 = blockIdx.y * 128;
    int tid = threadIdx.x;
    int tx = tid & 15;
    int ty = tid >> 4;
    int r  = tid & 127;
    int part = tid >> 7;

    unsigned long long acc[8][4];
#pragma unroll
    for (int i = 0; i < 8; i++)
#pragma unroll
        for (int p = 0; p < 4; p++) acc[i][p] = 0ull;

    for (int k0 = 0; k0 < Ee; k0 += 16) {
        __syncthreads();
        {
            int m = m0 + r;
#pragma unroll
            for (int j = 0; j < 2; j++) {
                int k = k0 + part * 8 + j * 4;
                float4 v = make_float4(0.f, 0.f, 0.f, 0.f);
                if (m < Vv && k + 3 < Ee)
                    v = *(const float4*)&A[(size_t)m * Ee + k];
                int kk = part * 8 + j * 4;
                float* dst0 = &As2[kk * 264 + 2 * r];
                *(float2*)(dst0)           = make_float2(v.x, v.x);
                *(float2*)(dst0 + 264)     = make_float2(v.y, v.y);
                *(float2*)(dst0 + 2 * 264) = make_float2(v.z, v.z);
                *(float2*)(dst0 + 3 * 264) = make_float2(v.w, v.w);
            }
        }
        {
            int n = n0 + r;
#pragma unroll
            for (int j = 0; j < 2; j++) {
                int k = k0 + part * 8 + j * 4;
                float4 v = make_float4(0.f, 0.f, 0.f, 0.f);
                if (n < G4 && k + 3 < Ee)
                    v = *(const float4*)&W[(size_t)n * Ee + k];
                int kk = part * 8 + j * 4;
                Wsm[kk * 132 + r]           = v.x;
                Wsm[(kk + 1) * 132 + r]     = v.y;
                Wsm[(kk + 2) * 132 + r]     = v.z;
                Wsm[(kk + 3) * 132 + r]     = v.w;
            }
        }
        __syncthreads();
#pragma unroll 4
        for (int kk = 0; kk < 16; kk++) {
            const float* arow = &As2[kk * 264 + ty * 16];
            const float* wrow = &Wsm[kk * 132 + tx * 8];
            ulonglong2 a01 = *(const ulonglong2*)(arow);
            ulonglong2 a23 = *(const ulonglong2*)(arow + 4);
            ulonglong2 a45 = *(const ulonglong2*)(arow + 8);
            ulonglong2 a67 = *(const ulonglong2*)(arow + 12);
            ulonglong2 w03 = *(const ulonglong2*)(wrow);
            ulonglong2 w47 = *(const ulonglong2*)(wrow + 4);
            unsigned long long av[8] = {a01.x, a01.y, a23.x, a23.y,
                                        a45.x, a45.y, a67.x, a67.y};
            unsigned long long wv[4] = {w03.x, w03.y, w47.x, w47.y};
#pragma unroll
            for (int i = 0; i < 8; i++)
#pragma unroll
                for (int p = 0; p < 4; p++) fma2(acc[i][p], av[i], wv[p]);
        }
    }

    float bias[8];
#pragma unroll
    for (int j = 0; j < 8; j++) {
        int n = n0 + tx * 8 + j;
        bias[j] = (n < G4) ? (b1[n] + b2[n]) : 0.f;
    }
#pragma unroll
    for (int i = 0; i < 8; i++) {
        int m = m0 + ty * 8 + i;
        if (m >= Vv) continue;
        float vals[8];
#pragma unroll
        for (int p = 0; p < 4; p++) {
            float2 u = u2f(acc[i][p]);
            vals[2 * p]     = u.x + bias[2 * p];
            vals[2 * p + 1] = u.y + bias[2 * p + 1];
        }
        int nb = n0 + tx * 8;
        if (nb + 7 < G4) {
            *(float4*)&C[(size_t)m * G4 + nb]     = make_float4(vals[0], vals[1], vals[2], vals[3]);
            *(float4*)&C[(size_t)m * G4 + nb + 4] = make_float4(vals[4], vals[5], vals[6], vals[7]);
        } else {
#pragma unroll
            for (int j = 0; j < 8; j++)
                if (nb + j < G4) C[(size_t)m * G4 + nb + j] = vals[j];
        }
    }
}

// ============================================================
// Phase 2: PERSISTENT bidirectional LSTM, v2.
// grid (15,4,2) = 120 resident blocks, 320 threads.
// Changes vs v1: flag-release barrier (no atomic polling, no nanosleep),
// double-buffered h staging (latency overlap, 6 syncs/step),
// tokens staged in smem, unroll 4, launch_bounds regs headroom.
// ============================================================
__global__ void __launch_bounds__(320, 1)
lstm_persist(const int* __restrict__ x,
             const float* __restrict__ whhf, const float* __restrict__ whhb)
{
    extern __shared__ __align__(16) float smem[];
    float* Ws   = smem;                     // [300][80] (hl*4+g inner)  96,000B
    float* Hbuf0 = smem + 24000;            // [60][132] b-duplicated    31,680B
    float* Hbuf1 = smem + 24000 + 7920;     //                            31,680B
    int*   stok  = (int*)(smem + 24000 + 15840);   // 64 tokens

    int htile = blockIdx.x;
    int btile = blockIdx.y;
    int dir   = blockIdx.z;
    int h0 = htile * HT;
    int b0 = btile * BT;

    const float* whh = dir ? whhb : whhf;
    const float* tbl = dir ? g_table_b : g_table_f;
    float* hbase = dir ? g_hb : g_hf;
    unsigned* cnt = &g_bar2[(dir * 4 + btile) * 64];
    volatile unsigned* flag = (volatile unsigned*)&g_bar2[(dir * 4 + btile) * 64 + 32];

    int tid = threadIdx.x;
    int tx = tid % HT;        // h lane (0..19)
    int ty = tid / HT;        // b quad (0..15)
    int h  = h0 + tx;

    // load W tile once: Ws[k*80 + hl*4 + g] = whh[(g*300 + h0+hl)*300 + k]
    for (int idx = tid; idx < HT * 4 * Hd; idx += 320) {
        int k = idx % Hd;
        int q = idx / Hd;
        int g = q & 3, hl = q >> 2;
        Ws[k * 80 + q] = whh[((size_t)g * Hd + h0 + hl) * Hd + k];
    }

    float cst[4] = {0.f, 0.f, 0.f, 0.f};

    for (int s = 0; s < Sd; s++) {
        int time = dir ? (Sd - 1 - s) : s;

        // stage tokens for this step
        if (tid < 64) {
            int t = x[(b0 + tid) * Sd + time];
            stok[tid] = ((unsigned)t < (unsigned)Vv) ? t : 0;
        }
        __syncthreads();   // tokens visible; also covers initial Ws load (s==0)

        // prefetch table rows (consumed in epilogue; hidden by GEMM)
        float tv[4][4];
#pragma unroll
        for (int i = 0; i < 4; i++) {
            const float* trow = tbl + (size_t)stok[ty * 4 + i] * G4 + h;
#pragma unroll
            for (int g = 0; g < 4; g++) tv[i][g] = __ldg(trow + g * Hd);
        }

        unsigned long long acc[4][2] = {{0ull,0ull},{0ull,0ull},{0ull,0ull},{0ull,0ull}};

        if (s > 0) {
            int ptime = dir ? (time + 1) : (time - 1);
            const float* hprev = hbase + (size_t)ptime * Hd * Bd;

            // stage chunk 0
            {
                const float* hp = hprev + b0;
#pragma unroll
                for (int l = 0; l < 3; l++) {
                    int j = tid + l * 320;
                    int c = j >> 4, r = j & 15;
                    float4 v = *(const float4*)&hp[(size_t)c * Bd + r * 4];
                    float* d = Hbuf0 + c * 132 + r * 8;
                    *(float4*)d       = make_float4(v.x, v.x, v.y, v.y);
                    *(float4*)(d + 4) = make_float4(v.z, v.z, v.w, v.w);
                }
            }
            float* bufs[2] = {Hbuf0, Hbuf1};
            int cur = 0;
#pragma unroll
            for (int chunk = 0; chunk < 5; chunk++) {
                __syncthreads();    // buf[cur] ready
                if (chunk < 4) {    // prefetch next chunk into other buffer
                    const float* hp = hprev + (size_t)((chunk + 1) * 60) * Bd + b0;
                    float* dst = bufs[cur ^ 1];
#pragma unroll
                    for (int l = 0; l < 3; l++) {
                        int j = tid + l * 320;
                        int c = j >> 4, r = j & 15;
                        float4 v = *(const float4*)&hp[(size_t)c * Bd + r * 4];
                        float* d = dst + c * 132 + r * 8;
                        *(float4*)d       = make_float4(v.x, v.x, v.y, v.y);
                        *(float4*)(d + 4) = make_float4(v.z, v.z, v.w, v.w);
                    }
                }
                const float* wsb = Ws + chunk * 60 * 80 + tx * 4;
                const float* hb  = bufs[cur] + ty * 8;
#pragma unroll 4
                for (int kk = 0; kk < 60; kk++) {
                    ulonglong2 w03 = *(const ulonglong2*)(wsb + kk * 80);
                    ulonglong2 h01 = *(const ulonglong2*)(hb + kk * 132);
                    ulonglong2 h23 = *(const ulonglong2*)(hb + kk * 132 + 4);
                    fma2(acc[0][0], h01.x, w03.x); fma2(acc[0][1], h01.x, w03.y);
                    fma2(acc[1][0], h01.y, w03.x); fma2(acc[1][1], h01.y, w03.y);
                    fma2(acc[2][0], h23.x, w03.x); fma2(acc[2][1], h23.x, w03.y);
                    fma2(acc[3][0], h23.y, w03.x); fma2(acc[3][1], h23.y, w03.y);
                }
                cur ^= 1;
            }
        }

        // epilogue: gates -> activations -> h,c
        float hnew[4];
#pragma unroll
        for (int i = 0; i < 4; i++) {
            float2 p0 = u2f(acc[i][0]);   // (gate_i, gate_f)
            float2 p1 = u2f(acc[i][1]);   // (gate_g, gate_o)
            float ai = clampg(p0.x + tv[i][0]);
            float af = clampg(p0.y + tv[i][1]);
            float ag = clampg(p1.x + tv[i][2]);
            float ao = clampg(p1.y + tv[i][3]);
            float ig = 1.f / (1.f + expf(-ai));
            float fg = 1.f / (1.f + expf(-af));
            float gg = tanhf(ag);
            float og = 1.f / (1.f + expf(-ao));
            float cnew = fg * cst[i] + ig * gg;
            cst[i] = cnew;
            hnew[i] = og * tanhf(clampg(cnew));
        }
        *(float4*)&hbase[((size_t)time * Hd + h) * Bd + b0 + ty * 4] =
            make_float4(hnew[0], hnew[1], hnew[2], hnew[3]);

        // flag-release group barrier (15 blocks sharing dir+btile)
        if (s < Sd - 1) {
            __syncthreads();
            if (tid == 0) {
                __threadfence();
                unsigned v = atomicAdd(cnt, 1u) + 1u;
                if (v == (unsigned)NHT * (unsigned)(s + 1)) {
                    atomicExch((unsigned*)flag, (unsigned)(s + 1));
                } else {
                    while (*flag < (unsigned)(s + 1)) { }
                }
                __threadfence();
            }
            __syncthreads();
        }
    }
}

// ============================================================
// Phase 3a: emissions, fp64 accumulation. Block per s, thread per b.
// ============================================================
__global__ void __launch_bounds__(256)
emis_kernel(const float* __restrict__ wproj, const float* __restrict__ bproj)
{
    __shared__ float wp[Td * 2 * Hd];
    int s = blockIdx.x;
    int b = threadIdx.x;
    for (int i = threadIdx.x; i < Td * 2 * Hd; i += blockDim.x) wp[i] = wproj[i];
    __syncthreads();

    const float* f  = g_hf + (size_t)s * Hd * Bd;
    const float* bk = g_hb + (size_t)s * Hd * Bd;
    double acc[Td] = {};
    for (int j = 0; j < Hd; j++) {
        double v = (double)f[(size_t)j * Bd + b];
#pragma unroll
        for (int t = 0; t < Td; t++) acc[t] += v * (double)wp[t * 2 * Hd + j];
    }
    for (int j = 0; j < Hd; j++) {
        double v = (double)bk[(size_t)j * Bd + b];
#pragma unroll
        for (int t = 0; t < Td; t++) acc[t] += v * (double)wp[t * 2 * Hd + Hd + j];
    }
#pragma unroll
    for (int t = 0; t < Td; t++)
        g_em[((size_t)s * Bd + b) * Td + t] = acc[t] + (double)bproj[t];
}

// ============================================================
// Phase 3b: Viterbi DP + backtrack, fp64, float32 tag output.
// ============================================================
__global__ void viterbi_kernel(const float* __restrict__ start_t, const float* __restrict__ end_t,
                               const float* __restrict__ trans, float* __restrict__ out)
{
    __shared__ double tr[Td][Td];
    if (threadIdx.x < Td * Td)
        tr[threadIdx.x / Td][threadIdx.x % Td] = (double)trans[threadIdx.x];
    __syncthreads();
    int b = blockIdx.x * blockDim.x + threadIdx.x;
    if (b >= Bd) return;

    double sc[Td];
#pragma unroll
    for (int t = 0; t < Td; t++)
        sc[t] = (double)start_t[t] + g_em[(size_t)b * Td + t];

    for (int s = 1; s < Sd; s++) {
        const double* em = &g_em[((size_t)s * Bd + b) * Td];
        double ns[Td];
#pragma unroll
        for (int tn = 0; tn < Td; tn++) {
            double best = sc[0] + tr[0][tn];
            int arg = 0;
#pragma unroll
            for (int tp = 1; tp < Td; tp++) {
                double v = sc[tp] + tr[tp][tn];
                if (v > best) { best = v; arg = tp; }
            }
            ns[tn] = best + em[tn];
            g_bp[((size_t)(s - 1) * Bd + b) * Td + tn] = (unsigned char)arg;
        }
#pragma unroll
        for (int t = 0; t < Td; t++) sc[t] = ns[t];
    }

    int last = 0;
    double best = sc[0] + (double)end_t[0];
#pragma unroll
    for (int t = 1; t < Td; t++) {
        double v = sc[t] + (double)end_t[t];
        if (v > best) { best = v; last = t; }
    }
    out[b * Sd + (Sd - 1)] = (float)last;
    int tag = last;
    for (int s = Sd - 2; s >= 0; s--) {
        tag = g_bp[((size_t)s * Bd + b) * Td + tag];
        out[b * Sd + s] = (float)tag;
    }
}

// ============================================================
extern "C" void kernel_launch(void* const* d_in, const int* in_sizes, int n_in,
                              void* d_out, int out_size)
{
    static const int expA[15] = {65536, 9000000, 360000, 360000, 1200, 1200,
                                 360000, 360000, 1200, 1200, 5400, 9, 9, 9, 81};
    bool okA = (n_in == 15), okA4 = (n_in == 15);
    for (int i = 0; i < 15 && n_in == 15; i++) {
        if (in_sizes[i] != expA[i])     okA  = false;
        if (in_sizes[i] != expA[i] * 4) okA4 = false;
    }
    if (!okA && !okA4) {
        SizePack sp; sp.n = n_in;
        for (int i = 0; i < 16; i++) sp.v[i] = (i < n_in) ? in_sizes[i] : -1;
        bad_layout_kernel<<<1, 1>>>(sp);
        return;
    }

    const int*   x       = (const int*)  d_in[0];
    const float* emb     = (const float*)d_in[1];
    const float* wihf    = (const float*)d_in[2];
    const float* whhf    = (const float*)d_in[3];
    const float* bihf    = (const float*)d_in[4];
    const float* bhhf    = (const float*)d_in[5];
    const float* wihb    = (const float*)d_in[6];
    const float* whhb    = (const float*)d_in[7];
    const float* bihb    = (const float*)d_in[8];
    const float* bhhb    = (const float*)d_in[9];
    const float* wproj   = (const float*)d_in[10];
    const float* bproj   = (const float*)d_in[11];
    const float* start_t = (const float*)d_in[12];
    const float* end_t   = (const float*)d_in[13];
    const float* trans   = (const float*)d_in[14];
    float* out = (float*)d_out;

    zero_bar_kernel<<<1, 512>>>();

    dim3 gt((G4 + 127) / 128, (Vv + 127) / 128, 2);
    table_gemm<<<gt, 256>>>(emb, wihf, wihb, bihf, bhhf, bihb, bhhb);

    int smem_bytes = (24000 + 15840 + 64) * sizeof(float);   // 159,616 B
    cudaFuncSetAttribute(lstm_persist,
                         cudaFuncAttributeMaxDynamicSharedMemorySize, smem_bytes);
    dim3 gp(NHT, NBT, 2);
    lstm_persist<<<gp, 320, smem_bytes>>>(x, whhf, whhb);

    emis_kernel<<<Sd, Bd>>>(wproj, bproj);
    viterbi_kernel<<<2, 128>>>(start_t, end_t, trans, out);
}